// round 1
// baseline (speedup 1.0000x reference)
#include <cuda_runtime.h>

// Shapes (fixed by the problem)
#define N_SAMP 32768
#define D_DIM  256
#define M_ST   4
#define K_CODE 1024

// Output layout (element offsets into f32 d_out)
#define OFF_XQ   0
#define OFF_LOSS 8388608
#define OFF_IDX  8388609
#define OFF_EMB  8519681
#define OFF_AVG  9568257
#define OFF_CS   10616833
#define OUT_TOT  10620929

// Scratch (device globals — no allocation allowed)
__device__ __align__(16) float g_part[256 * 256];   // per-block column partial sums of x
__device__ __align__(16) float g_Sx[256];           // column sums of x
__device__ __align__(16) float g_P[5 * 256];        // P_i = sum_{j<i} emb[j,0,:]; g_P[4*256+d] = s[d]
__device__ __align__(16) float g_invw[4 * 1024];    // 1/weights per stage/code

// ---------------------------------------------------------------------------
// Kernel A: partial column sums of x. 256 blocks x 256 threads; block b sums
// rows [b*128, b*128+128). Thread t owns column t -> fully coalesced loads.
// ---------------------------------------------------------------------------
__global__ void colsum_partial(const float* __restrict__ x) {
    const int d = threadIdx.x;
    const int b = blockIdx.x;
    const float* xp = x + (size_t)b * 128 * D_DIM + d;
    float acc = 0.f;
#pragma unroll 8
    for (int r = 0; r < 128; ++r) acc += xp[(size_t)r * D_DIM];
    g_part[b * D_DIM + d] = acc;
}

// ---------------------------------------------------------------------------
// Kernel B: finalize Sx (fixed-order reduce of 256 partials) and prefix sums
// P_i of emb[i,0,:]. 1 block x 256 threads.
// ---------------------------------------------------------------------------
__global__ void finalize_sums(const float* __restrict__ emb) {
    const int d = threadIdx.x;
    float s = 0.f;
    for (int b = 0; b < 256; ++b) s += g_part[b * D_DIM + d];
    g_Sx[d] = s;
    float p = 0.f;
    g_P[d] = 0.f;  // P_0 = 0
#pragma unroll
    for (int i = 0; i < M_ST; ++i) {
        p += emb[(size_t)i * K_CODE * D_DIM + d];  // emb[i, 0, d]
        g_P[(i + 1) * D_DIM + d] = p;              // g_P[4*256+d] = s[d] = sum of all 4
    }
}

// ---------------------------------------------------------------------------
// Kernel C: new cluster_size, n, weights. 4 blocks (stage) x 1024 threads (code).
// Fixed-order shared-mem tree reduction -> deterministic.
// ---------------------------------------------------------------------------
__global__ void csize_weights(const float* __restrict__ cs_in, float* __restrict__ out,
                              int out_size) {
    const int i = blockIdx.x;
    const int k = threadIdx.x;
    const float cnt = (k == 0) ? 32768.0f : 0.0f;
    const float c = cs_in[i * K_CODE + k] * 0.99f + cnt * 0.01f;
    const int o = OFF_CS + i * K_CODE + k;
    if (o < out_size) out[o] = c;

    __shared__ float red[1024];
    red[k] = c;
    __syncthreads();
    for (int s = 512; s > 0; s >>= 1) {
        if (k < s) red[k] += red[k + s];
        __syncthreads();
    }
    const float n = red[0];
    const float w = (c + 1e-5f) / (n + 1024.0f * 1e-5f) * n;
    g_invw[i * K_CODE + k] = 1.0f / w;
}

// ---------------------------------------------------------------------------
// Kernel D1: x_q_total (broadcast s[d]) + loss + indices (zeros).
// float4 over [0, 8519680), one scalar tail. OFF_XQ=0 so float4 is aligned.
// ---------------------------------------------------------------------------
__global__ void write_xq(float* __restrict__ out, int out_size) {
    const long t = (long)blockIdx.x * blockDim.x + threadIdx.x;  // float4 index
    const long NQ4 = 8388608 / 4;  // x_q region in float4
    const long NT4 = 8519680 / 4;  // x_q + loss + indices (minus last scalar)
    if (t < NQ4) {
        const float4 v = ((const float4*)(g_P + 4 * D_DIM))[t & 63];
        if (t * 4 + 3 < out_size) ((float4*)out)[t] = v;
    } else if (t < NT4) {
        if (t * 4 + 3 < out_size) ((float4*)out)[t] = make_float4(0.f, 0.f, 0.f, 0.f);
    } else if (t == NT4) {
        if (8519680 < out_size) out[8519680] = 0.f;
    }
}

// ---------------------------------------------------------------------------
// Kernel D2: new_avg and new_emb for all (i,k,d). Scalar coalesced stores
// (output offsets are odd, so no float4 on stores).
// ---------------------------------------------------------------------------
__global__ void write_emb_avg(const float* __restrict__ avg_in, float* __restrict__ out,
                              int out_size) {
    const int t = blockIdx.x * blockDim.x + threadIdx.x;
    if (t >= M_ST * K_CODE * D_DIM) return;
    const int d = t & (D_DIM - 1);
    const int row = t >> 8;          // i*K + k
    const int k = row & (K_CODE - 1);
    const int i = row >> 10;
    float sum_term = 0.0f;
    if (k == 0) sum_term = g_Sx[d] - 32768.0f * g_P[i * D_DIM + d];
    const float na = 0.99f * avg_in[t] + 0.01f * sum_term;
    const int oa = OFF_AVG + t;
    const int oe = OFF_EMB + t;
    if (oa < out_size) out[oa] = na;
    if (oe < out_size) out[oe] = na * g_invw[row];
}

extern "C" void kernel_launch(void* const* d_in, const int* in_sizes, int n_in,
                              void* d_out, int out_size) {
    const float* x   = (const float*)d_in[0];  // [N, D]
    const float* emb = (const float*)d_in[1];  // [M, K, D]
    const float* avg = (const float*)d_in[2];  // [M, K, D]
    const float* cs  = (const float*)d_in[3];  // [M, K]
    float* out = (float*)d_out;

    colsum_partial<<<256, 256>>>(x);
    finalize_sums<<<1, 256>>>(emb);
    csize_weights<<<4, 1024>>>(cs, out, out_size);

    // x_q_total + loss + indices: 2129921 work items (float4 units + 1 tail)
    write_xq<<<(2129921 + 255) / 256, 256>>>(out, out_size);

    // embs + avgs: 4*1024*256 = 1048576 elements
    write_emb_avg<<<(M_ST * K_CODE * D_DIM + 255) / 256, 256>>>(avg, out, out_size);
}

// round 2
// speedup vs baseline: 1.4110x; 1.4110x over previous
#include <cuda_runtime.h>

// Shapes (fixed by the problem)
#define N_SAMP 32768
#define D_DIM  256
#define M_ST   4
#define K_CODE 1024

// Output layout (element offsets into f32 d_out)
#define OFF_XQ   0
#define OFF_LOSS 8388608
#define OFF_IDX  8388609
#define OFF_EMB  8519681
#define OFF_AVG  9568257
#define OFF_CS   10616833
#define OUT_TOT  10620929

// Scratch (device globals — no allocation allowed)
__device__ __align__(16) float g_part[256 * 256];   // per-block column partial sums of x
__device__ __align__(16) float g_invw[4 * 1024];    // 1/weights per stage/code

// ---------------------------------------------------------------------------
// K1: fused independent work, dispatched by blockIdx range (blockDim = 256):
//   [0,256)    colsum partials of x   -> g_part
//   [256,260)  cluster_size out + invw -> g_invw
//   [260,388)  zero-fill loss+indices region
//   [388,2436) x_q_total writes (s[d] recomputed from emb directly)
// ---------------------------------------------------------------------------
__global__ void k1_fused(const float* __restrict__ x,
                         const float* __restrict__ emb,
                         const float* __restrict__ cs_in,
                         float* __restrict__ out, int out_size) {
    const int b = blockIdx.x;
    const int tid = threadIdx.x;

    if (b < 256) {
        // ---- colsum partial: block b sums rows [b*128, b*128+128), col = tid
        const float* xp = x + (size_t)b * 128 * D_DIM + tid;
        float acc = 0.f;
#pragma unroll 8
        for (int r = 0; r < 128; ++r) acc += xp[(size_t)r * D_DIM];
        g_part[b * D_DIM + tid] = acc;
    } else if (b < 260) {
        // ---- csize + weights for stage i; 4 codes per thread
        const int i = b - 256;
        float c[4];
        float psum;
        {
            float c0 = cs_in[i * K_CODE + tid]       * 0.99f + ((tid == 0) ? 327.68f : 0.f);
            float c1 = cs_in[i * K_CODE + tid + 256] * 0.99f;
            float c2 = cs_in[i * K_CODE + tid + 512] * 0.99f;
            float c3 = cs_in[i * K_CODE + tid + 768] * 0.99f;
            c[0] = c0; c[1] = c1; c[2] = c2; c[3] = c3;
            psum = ((c0 + c1) + c2) + c3;
        }
#pragma unroll
        for (int j = 0; j < 4; ++j) {
            const int o = OFF_CS + i * K_CODE + tid + j * 256;
            if (o < out_size) out[o] = c[j];
        }
        __shared__ float red[256];
        red[tid] = psum;
        __syncthreads();
        for (int s = 128; s > 0; s >>= 1) {
            if (tid < s) red[tid] += red[tid + s];
            __syncthreads();
        }
        const float n = red[0];
#pragma unroll
        for (int j = 0; j < 4; ++j) {
            const float w = (c[j] + 1e-5f) / (n + 1024.0f * 1e-5f) * n;
            g_invw[i * K_CODE + tid + j * 256] = 1.0f / w;
        }
    } else if (b < 388) {
        // ---- zero-fill loss + indices: 32768 float4 starting at float4 idx 2097152,
        //      plus one scalar tail at element 8519680
        const int j = (b - 260) * 256 + tid;             // [0, 32768)
        const long e4 = 2097152L + j;
        if (e4 * 4 + 3 < out_size)
            ((float4*)out)[e4] = make_float4(0.f, 0.f, 0.f, 0.f);
        if (j == 0 && 8519680 < out_size) out[8519680] = 0.f;
    } else {
        // ---- x_q_total: 524288 threads, each stores 4 float4 at stride 524288.
        // s4 recomputed directly from emb (no cross-block dependency).
        const long u = (long)(b - 388) * 256 + tid;      // [0, 524288)
        const int c4 = (int)(u & 63);                    // float4 column
        const float4* e4p = (const float4*)emb;
        float4 s0 = e4p[0 * 65536 + c4];
        float4 s1 = e4p[1 * 65536 + c4];
        float4 s2 = e4p[2 * 65536 + c4];
        float4 s3 = e4p[3 * 65536 + c4];
        float4 s;
        s.x = ((s0.x + s1.x) + s2.x) + s3.x;
        s.y = ((s0.y + s1.y) + s2.y) + s3.y;
        s.z = ((s0.z + s1.z) + s2.z) + s3.z;
        s.w = ((s0.w + s1.w) + s2.w) + s3.w;
#pragma unroll
        for (int j = 0; j < 4; ++j) {
            const long e4 = u + (long)j * 524288;        // < 2097152
            if (e4 * 4 + 3 < out_size) ((float4*)out)[e4] = s;
        }
    }
}

// ---------------------------------------------------------------------------
// K2: emb/avg outputs (blockDim = 256):
//   [0,1024)    regular rows (k != 0): 1024 elements/block, stride-256 per thread
//   [1024,1028) k==0 row of stage i: reduce g_part -> Sx, then write 256 elems
// ---------------------------------------------------------------------------
__global__ void k2_emb_avg(const float* __restrict__ emb,
                           const float* __restrict__ avg,
                           float* __restrict__ out, int out_size) {
    const int b = blockIdx.x;
    const int tid = threadIdx.x;

    if (b < 1024) {
#pragma unroll
        for (int j = 0; j < 4; ++j) {
            const int t = b * 1024 + j * 256 + tid;      // element index
            const int row = t >> 8;                      // i*K + k
            const int k = row & (K_CODE - 1);
            if (k == 0) continue;                        // handled by special blocks
            const float na = 0.99f * avg[t];             // sum_term == 0 for k != 0
            const int oa = OFF_AVG + t;
            const int oe = OFF_EMB + t;
            if (oa < out_size) out[oa] = na;
            if (oe < out_size) out[oe] = na * g_invw[row];
        }
    } else {
        // stage i, row k==0: need Sx[d] = total column sum of x
        const int i = b - 1024;
        const int d = tid;
        float sx = 0.f;
        for (int p = 0; p < 256; ++p) sx += g_part[p * D_DIM + d];
        // P_i[d] = sum_{j<i} emb[j,0,d]
        float pi = 0.f;
        for (int j = 0; j < i; ++j) pi += emb[(size_t)j * K_CODE * D_DIM + d];
        const float sum_term = sx - 32768.0f * pi;
        const int t = i * K_CODE * D_DIM + d;            // element index of (i, 0, d)
        const float na = 0.99f * avg[t] + 0.01f * sum_term;
        const float iw = g_invw[i * K_CODE];             // k == 0
        const int oa = OFF_AVG + t;
        const int oe = OFF_EMB + t;
        if (oa < out_size) out[oa] = na;
        if (oe < out_size) out[oe] = na * iw;
    }
}

extern "C" void kernel_launch(void* const* d_in, const int* in_sizes, int n_in,
                              void* d_out, int out_size) {
    const float* x   = (const float*)d_in[0];  // [N, D]
    const float* emb = (const float*)d_in[1];  // [M, K, D]
    const float* avg = (const float*)d_in[2];  // [M, K, D]
    const float* cs  = (const float*)d_in[3];  // [M, K]
    float* out = (float*)d_out;

    k1_fused<<<2436, 256>>>(x, emb, cs, out, out_size);
    k2_emb_avg<<<1028, 256>>>(emb, avg, out, out_size);
}

// round 3
// speedup vs baseline: 1.5595x; 1.1052x over previous
#include <cuda_runtime.h>

// Shapes (fixed by the problem)
#define N_SAMP 32768
#define D_DIM  256
#define M_ST   4
#define K_CODE 1024

// Output layout (element offsets into f32 d_out)
#define OFF_XQ   0
#define OFF_LOSS 8388608
#define OFF_IDX  8388609
#define OFF_EMB  8519681
#define OFF_AVG  9568257
#define OFF_CS   10616833
#define OUT_TOT  10620929

// Scratch (device globals — no allocation allowed)
__device__ __align__(16) float g_part[256 * 256];   // per-block column partials of x

// ---------------------------------------------------------------------------
// K1: fused independent work, blockDim = 256, grid = 2948:
//   [0,256)      colsum partials of x (float4)          -> g_part
//   [256,260)    cluster_size outputs
//   [260,388)    zero-fill loss + indices
//   [388,2436)   x_q_total broadcast writes
//   [2436,2948)  emb/avg outputs for k != 0 (invw recomputed per block)
// ---------------------------------------------------------------------------
__global__ void __launch_bounds__(256) k1_fused(
        const float* __restrict__ x,
        const float* __restrict__ emb,
        const float* __restrict__ avg,
        const float* __restrict__ cs_in,
        float* __restrict__ out, int out_size) {
    const int b = blockIdx.x;
    const int tid = threadIdx.x;

    if (b < 256) {
        // ---- colsum partial: block b covers rows [b*128, b*128+128).
        // thread: r_off = tid>>6 (row phase 0..3), c4 = tid&63 (float4 column).
        const int r_off = tid >> 6;
        const int c4 = tid & 63;
        const float4* x4 = (const float4*)x;
        float4 acc = make_float4(0.f, 0.f, 0.f, 0.f);
        const long base = (long)b * 128 * 64 + c4;
#pragma unroll 8
        for (int r = r_off; r < 128; r += 4) {
            float4 v = x4[base + (long)r * 64];
            acc.x += v.x; acc.y += v.y; acc.z += v.z; acc.w += v.w;
        }
        __shared__ float4 s4[256];
        s4[tid] = acc;
        __syncthreads();
        if (tid < 64) {
            float4 a = s4[tid], b1 = s4[tid + 64], c = s4[tid + 128], d = s4[tid + 192];
            float4 r;
            r.x = ((a.x + b1.x) + c.x) + d.x;
            r.y = ((a.y + b1.y) + c.y) + d.y;
            r.z = ((a.z + b1.z) + c.z) + d.z;
            r.w = ((a.w + b1.w) + c.w) + d.w;
            ((float4*)g_part)[b * 64 + tid] = r;
        }
    } else if (b < 260) {
        // ---- cluster_size outputs for stage i
        const int i = b - 256;
#pragma unroll
        for (int j = 0; j < 4; ++j) {
            const int k = tid + j * 256;
            const float c = cs_in[i * K_CODE + k] * 0.99f +
                            ((k == 0) ? 327.68f : 0.f);
            const int o = OFF_CS + i * K_CODE + k;
            if (o < out_size) out[o] = c;
        }
    } else if (b < 388) {
        // ---- zero-fill loss + indices: float4 idx [2097152, 2129920) + tail scalar
        const int j = (b - 260) * 256 + tid;             // [0, 32768)
        const long e4 = 2097152L + j;
        if (e4 * 4 + 3 < out_size)
            ((float4*)out)[e4] = make_float4(0.f, 0.f, 0.f, 0.f);
        if (j == 0 && 8519680 < out_size) out[8519680] = 0.f;
    } else if (b < 2436) {
        // ---- x_q_total: each thread stores 4 float4 at stride 524288
        const long u = (long)(b - 388) * 256 + tid;      // [0, 524288)
        const int c4 = (int)(u & 63);
        const float4* e4p = (const float4*)emb;
        float4 s0 = e4p[0 * 65536 + c4];
        float4 s1 = e4p[1 * 65536 + c4];
        float4 s2 = e4p[2 * 65536 + c4];
        float4 s3 = e4p[3 * 65536 + c4];
        float4 s;
        s.x = ((s0.x + s1.x) + s2.x) + s3.x;
        s.y = ((s0.y + s1.y) + s2.y) + s3.y;
        s.z = ((s0.z + s1.z) + s2.z) + s3.z;
        s.w = ((s0.w + s1.w) + s2.w) + s3.w;
#pragma unroll
        for (int j = 0; j < 4; ++j) {
            const long e4 = u + (long)j * 524288;        // < 2097152
            if (e4 * 4 + 3 < out_size) ((float4*)out)[e4] = s;
        }
    } else {
        // ---- emb/avg for k != 0. blk in [0,512): 128 blocks per stage, 8 rows each.
        const int blk = b - 2436;
        const int i = blk >> 7;                          // stage
        const int r0 = (blk & 127) * 8;                  // first k of this block
        // n_i = 0.99 * sum(cs[i,:]) + 327.68  (L2-hot 4KB reduction)
        __shared__ float red[256];
        {
            const float* csr = cs_in + i * K_CODE;
            float s = ((csr[tid] + csr[tid + 256]) + csr[tid + 512]) + csr[tid + 768];
            red[tid] = s;
            __syncthreads();
            for (int st = 128; st > 0; st >>= 1) {
                if (tid < st) red[tid] += red[tid + st];
                __syncthreads();
            }
        }
        const float n = 0.99f * red[0] + 327.68f;
        const float denom = n + 1024.0f * 1e-5f;
#pragma unroll
        for (int r = 0; r < 8; ++r) {
            const int k = r0 + r;
            if (k == 0) continue;                        // handled by K2
            const int row = i * K_CODE + k;
            const float c = cs_in[row] * 0.99f;          // broadcast load
            const float w = (c + 1e-5f) / denom * n;
            const float iw = 1.0f / w;
            const int t = row * D_DIM + tid;
            const float na = 0.99f * avg[t];             // sum_term == 0 for k != 0
            const int oa = OFF_AVG + t;
            const int oe = OFF_EMB + t;
            if (oa < out_size) out[oa] = na;
            if (oe < out_size) out[oe] = na * iw;
        }
    }
}

// ---------------------------------------------------------------------------
// K2: k==0 rows only. 4 blocks x 1024 threads.
// ---------------------------------------------------------------------------
__global__ void __launch_bounds__(1024) k2_row0(
        const float* __restrict__ emb,
        const float* __restrict__ avg,
        const float* __restrict__ cs_in,
        float* __restrict__ out, int out_size) {
    const int i = blockIdx.x;
    const int tid = threadIdx.x;
    __shared__ float red[1024];

    // n_i
    red[tid] = cs_in[i * K_CODE + tid];
    __syncthreads();
    for (int st = 512; st > 0; st >>= 1) {
        if (tid < st) red[tid] += red[tid + st];
        __syncthreads();
    }
    const float n = 0.99f * red[0] + 327.68f;
    __syncthreads();

    // Sx: 4-way parallel reduction of 256 partials per column
    const int d = tid & 255;
    const int q = tid >> 8;
    float sx = 0.f;
#pragma unroll 8
    for (int p = 0; p < 64; ++p)
        sx += g_part[(q * 64 + p) * D_DIM + d];
    red[tid] = sx;
    __syncthreads();

    if (tid < 256) {
        const float sxt = ((red[tid] + red[tid + 256]) + red[tid + 512]) + red[tid + 768];
        float pi = 0.f;
        for (int j = 0; j < i; ++j) pi += emb[(size_t)j * K_CODE * D_DIM + tid];
        const float sum_term = sxt - 32768.0f * pi;
        const int t = i * K_CODE * D_DIM + tid;          // (i, 0, d=tid)
        const float na = 0.99f * avg[t] + 0.01f * sum_term;
        const float c0 = cs_in[i * K_CODE] * 0.99f + 327.68f;
        const float w = (c0 + 1e-5f) / (n + 1024.0f * 1e-5f) * n;
        const int oa = OFF_AVG + t;
        const int oe = OFF_EMB + t;
        if (oa < out_size) out[oa] = na;
        if (oe < out_size) out[oe] = na / w;
    }
}

extern "C" void kernel_launch(void* const* d_in, const int* in_sizes, int n_in,
                              void* d_out, int out_size) {
    const float* x   = (const float*)d_in[0];  // [N, D]
    const float* emb = (const float*)d_in[1];  // [M, K, D]
    const float* avg = (const float*)d_in[2];  // [M, K, D]
    const float* cs  = (const float*)d_in[3];  // [M, K]
    float* out = (float*)d_out;

    k1_fused<<<2948, 256>>>(x, emb, avg, cs, out, out_size);
    k2_row0<<<4, 1024>>>(emb, avg, cs, out, out_size);
}